// round 13
// baseline (speedup 1.0000x reference)
#include <cuda_runtime.h>
#include <cuda_bf16.h>
#include <cstdint>
#include <cstddef>

typedef unsigned long long ull;

#define Bn 8
#define Tn 2048
#define Dn 1024
#define HSn 64
#define TQ 8
#define VT 32
#define SPLIT 8
#define VLEN (Tn / SPLIT)          // 256
#define NTILE (VLEN / VT)          // 8
#define QPT 4                      // h-quarter stages per tile
#define NSTG (NTILE * QPT)         // 32

// Scratch (allocation-free rule: __device__ globals)
__device__ float          g_q [(size_t)Bn * Tn * HSn];   // [b][t][h] fp32 (rel term)
__device__ __nv_bfloat16  g_qh[(size_t)Bn * Tn * HSn];   // hi(8q)
__device__ __nv_bfloat16  g_ql[(size_t)Bn * Tn * HSn];   // lo(8q)
__device__ __nv_bfloat16  g_kh[(size_t)Bn * Tn * HSn];   // hi(k)
__device__ __nv_bfloat16  g_kl[(size_t)Bn * Tn * HSn];   // lo(k)
__device__ float          g_v [(size_t)Bn * Tn * HSn];   // [b][t][h]
__device__ float          g_s [(size_t)Bn * Tn * Tn];    // S = 8 q k^T  [b][t][v]
__device__ float g_po[SPLIT][(size_t)Bn * Tn * HSn];
__device__ float g_pm[SPLIT][Bn * Tn];
__device__ float g_pl[SPLIT][Bn * Tn];

// ---- f32x2 + wide-load helpers --------------------------------------------
__device__ __forceinline__ ull pack2(float a, float b) {
    ull r; asm("mov.b64 %0, {%1, %2};" : "=l"(r) : "f"(a), "f"(b)); return r;
}
__device__ __forceinline__ ull mul2(ull a, ull b) {
    ull r; asm("mul.rn.f32x2 %0, %1, %2;" : "=l"(r) : "l"(a), "l"(b)); return r;
}
__device__ __forceinline__ ull fma2(ull a, ull b, ull c) {
    ull r; asm("fma.rn.f32x2 %0, %1, %2, %3;" : "=l"(r) : "l"(a), "l"(b), "l"(c)); return r;
}
__device__ __forceinline__ void unpack2(float& lo, float& hi, ull v) {
    asm("mov.b64 {%0, %1}, %2;" : "=f"(lo), "=f"(hi) : "l"(v));
}
__device__ __forceinline__ void lds_v2(ull& a, ull& b, uint32_t addr) {
    asm volatile("ld.shared.v2.b64 {%0, %1}, [%2];" : "=l"(a), "=l"(b) : "r"(addr));
}
__device__ __forceinline__ ull lds64(uint32_t addr) {
    ull r; asm volatile("ld.shared.b64 %0, [%1];" : "=l"(r) : "r"(addr)); return r;
}
__device__ __forceinline__ ull ldg64(const void* p) {
    ull r; asm volatile("ld.global.nc.b64 %0, [%1];" : "=l"(r) : "l"(p)); return r;
}
__device__ __forceinline__ void sts_f32(uint32_t addr, float p) {
    asm volatile("st.shared.f32 [%0], %1;" :: "r"(addr), "f"(p) : "memory");
}
__device__ __forceinline__ void cp_async16(uint32_t dst, const void* src) {
    asm volatile("cp.async.cg.shared.global [%0], [%1], 16;" :: "r"(dst), "l"(src) : "memory");
}
#define CP_COMMIT()  asm volatile("cp.async.commit_group;" ::: "memory")
#define CP_WAIT(n)   asm volatile("cp.async.wait_group %0;" :: "n"(n) : "memory")

__device__ __forceinline__ uint32_t smem_u32(const void* p) {
    return (uint32_t)__cvta_generic_to_shared(p);
}

// ---------------------------------------------------------------------------
// K0: profiler pad (keeps attn at captured launch idx 3).
// ---------------------------------------------------------------------------
__global__ void prof_pad_kernel(float* __restrict__ dst)
{
    if (threadIdx.x == 0) dst[0] = -1e30f;   // overwritten before use
}

// ---------------------------------------------------------------------------
// K1: fused QKV projection (R5 core — measured best ~306us) + bf16 splits.
// ---------------------------------------------------------------------------
__global__ __launch_bounds__(256, 3)
void proj_kernel(const float* __restrict__ x,
                 const float* __restrict__ Wk, const float* __restrict__ bk,
                 const float* __restrict__ Wq, const float* __restrict__ bq,
                 const float* __restrict__ Wv, const float* __restrict__ bv)
{
    __shared__ float xsT[64 * 36];     // [k][tok]
    __shared__ float ws[64][193];      // [k][col]

    const int tid  = threadIdx.x;
    const int tok0 = blockIdx.x * 32;
    const int cl   = tid & 31;
    const int tr   = (tid >> 5) << 2;

    const uint32_t xsT_u = smem_u32(xsT);

    ull acc2[2][6];
#pragma unroll
    for (int i = 0; i < 2; ++i)
#pragma unroll
        for (int j = 0; j < 6; ++j) acc2[i][j] = 0ull;

    for (int k0 = 0; k0 < Dn; k0 += 64) {
        __syncthreads();
        for (int idx = tid; idx < 32 * 64; idx += 256) {
            int k = idx & 63, tk = idx >> 6;
            xsT[k * 36 + tk] = x[(size_t)(tok0 + tk) * Dn + k0 + k];
        }
        for (int idx = tid; idx < 192 * 64; idx += 256) {
            int k = idx & 63, col = idx >> 6;
            const float* Wsrc = (col < 64) ? Wk : ((col < 128) ? Wq : Wv);
            ws[k][col] = Wsrc[(size_t)(col & 63) * Dn + k0 + k];
        }
        __syncthreads();

#pragma unroll 8
        for (int k = 0; k < 64; ++k) {
            ull x2a, x2b;
            lds_v2(x2a, x2b, xsT_u + (uint32_t)(k * 36 + tr) * 4u);
#pragma unroll
            for (int j = 0; j < 6; ++j) {
                float wv = ws[k][cl + 32 * j];
                ull wd = pack2(wv, wv);
                acc2[0][j] = fma2(x2a, wd, acc2[0][j]);
                acc2[1][j] = fma2(x2b, wd, acc2[1][j]);
            }
        }
    }

#pragma unroll
    for (int j = 0; j < 6; ++j) {
        float a[4];
        unpack2(a[0], a[1], acc2[0][j]);
        unpack2(a[2], a[3], acc2[1][j]);
        int col = cl + 32 * j;
        int h = col & 63;
#pragma unroll
        for (int i = 0; i < 4; ++i) {
            int tokg = tok0 + tr + i;
            size_t off = (size_t)tokg * HSn + h;
            if (col < 64) {
                float r = a[i] + bk[h];
                __nv_bfloat16 rh = __float2bfloat16(r);
                g_kh[off] = rh;
                g_kl[off] = __float2bfloat16(r - __bfloat162float(rh));
            } else if (col < 128) {
                float qf = a[i] + bq[h];
                g_q[off] = qf;                         // fp32 (rel term)
                float q8 = 8.0f * qf;                  // fold sqrt(HS)=8
                __nv_bfloat16 qh8 = __float2bfloat16(q8);
                g_qh[off] = qh8;
                g_ql[off] = __float2bfloat16(q8 - __bfloat162float(qh8));
            } else {
                g_v[off] = a[i] + bv[h];
            }
        }
    }
}

// ---------------------------------------------------------------------------
// K2: S = 8 q k^T via warp-level HMMA (mma.sync m16n8k16 bf16), 3-pass split.
// Grid (16, 16, 8). CTA: 256 thr = 8 warps, tile M=128 x N=128, K=64.
// Warp tile 64x32 (wm = wid&1, wn = wid>>1): 4 m-frags x 4 n-frags.
// ---------------------------------------------------------------------------
#define GM 128
#define GN 128
#define SW128(off) ((off) ^ (((off) >> 3) & 0x70))
#define GS_AH 0
#define GS_AL 16384
#define GS_BH 32768
#define GS_BL 49152
#define GS_TOTAL 65536

__device__ __forceinline__ void ldmatrix_x4(uint32_t& r0, uint32_t& r1,
                                            uint32_t& r2, uint32_t& r3, uint32_t addr)
{
    asm volatile("ldmatrix.sync.aligned.m8n8.x4.shared.b16 {%0,%1,%2,%3}, [%4];"
                 : "=r"(r0), "=r"(r1), "=r"(r2), "=r"(r3) : "r"(addr));
}
__device__ __forceinline__ void mma_16816(float* c, const uint32_t* a,
                                          uint32_t b0, uint32_t b1)
{
    asm volatile(
        "mma.sync.aligned.m16n8k16.row.col.f32.bf16.bf16.f32 "
        "{%0,%1,%2,%3}, {%4,%5,%6,%7}, {%8,%9}, {%0,%1,%2,%3};"
        : "+f"(c[0]), "+f"(c[1]), "+f"(c[2]), "+f"(c[3])
        : "r"(a[0]), "r"(a[1]), "r"(a[2]), "r"(a[3]), "r"(b0), "r"(b1));
}

__global__ __launch_bounds__(256, 2)
void qk_gemm_kernel(float* __restrict__ S)
{
    extern __shared__ char gsm[];
    const uint32_t sm0 = smem_u32(gsm);
    const int tid  = threadIdx.x;
    const int wid  = tid >> 5;
    const int lane = tid & 31;
    const int t0   = blockIdx.x * GM;
    const int v0   = blockIdx.y * GN;
    const int b    = blockIdx.z;
    const int wm   = wid & 1;       // 0..1 : 64 m-rows each
    const int wn   = wid >> 1;      // 0..3 : 32 n-cols each

    // ---- stage A (qh/ql) and B (kh/kl), SW128-swizzled, 128B rows ----
    const char* qh = (const char*)(g_qh + ((size_t)b * Tn + t0) * HSn);
    const char* ql = (const char*)(g_ql + ((size_t)b * Tn + t0) * HSn);
    const char* kh = (const char*)(g_kh + ((size_t)b * Tn + v0) * HSn);
    const char* kl = (const char*)(g_kl + ((size_t)b * Tn + v0) * HSn);
    for (int idx = tid; idx < GM * 8; idx += 256) {
        int row = idx >> 3, c16 = idx & 7;
        int src = row * 128 + c16 * 16;
        uint32_t off = SW128((uint32_t)src);
        *(uint4*)(gsm + GS_AH + off) = *(const uint4*)(qh + src);
        *(uint4*)(gsm + GS_AL + off) = *(const uint4*)(ql + src);
        *(uint4*)(gsm + GS_BH + off) = *(const uint4*)(kh + src);
        *(uint4*)(gsm + GS_BL + off) = *(const uint4*)(kl + src);
    }
    __syncthreads();

    float c[4][4][4];
#pragma unroll
    for (int mi = 0; mi < 4; ++mi)
#pragma unroll
        for (int ni = 0; ni < 4; ++ni)
#pragma unroll
            for (int e = 0; e < 4; ++e) c[mi][ni][e] = 0.f;

    // ldmatrix per-lane sub-row/col (same formula for A .x4 and B-pair .x4)
    const int ar = (lane & 7) + ((lane >> 3) & 1) * 8;
    const int ac = (lane >> 4) * 8;

#pragma unroll
    for (int pass = 0; pass < 3; ++pass) {
        const uint32_t abase = sm0 + ((pass == 2) ? GS_AL : GS_AH);
        const uint32_t bbase = sm0 + ((pass == 1) ? GS_BL : GS_BH);
#pragma unroll
        for (int ks = 0; ks < 4; ++ks) {
            uint32_t a[4][4];
#pragma unroll
            for (int mi = 0; mi < 4; ++mi) {
                uint32_t byte = (uint32_t)((wm * 64 + mi * 16 + ar) * 128
                                           + (ks * 16 + ac) * 2);
                ldmatrix_x4(a[mi][0], a[mi][1], a[mi][2], a[mi][3],
                            abase + SW128(byte));
            }
            uint32_t bf[4][2];
#pragma unroll
            for (int np = 0; np < 2; ++np) {
                uint32_t byte = (uint32_t)((wn * 32 + np * 16 + ar) * 128
                                           + (ks * 16 + ac) * 2);
                uint32_t r0, r1, r2, r3;
                ldmatrix_x4(r0, r1, r2, r3, bbase + SW128(byte));
                bf[2 * np][0] = r0; bf[2 * np + 1][0] = r1;
                bf[2 * np][1] = r2; bf[2 * np + 1][1] = r3;
            }
#pragma unroll
            for (int mi = 0; mi < 4; ++mi)
#pragma unroll
                for (int ni = 0; ni < 4; ++ni)
                    mma_16816(c[mi][ni], a[mi], bf[ni][0], bf[ni][1]);
        }
    }

    // ---- epilogue: direct float2 stores ----
    float* Sb = S + (size_t)b * Tn * Tn;
#pragma unroll
    for (int mi = 0; mi < 4; ++mi) {
#pragma unroll
        for (int ni = 0; ni < 4; ++ni) {
            int gr = t0 + wm * 64 + mi * 16 + (lane >> 2);
            int gc = v0 + wn * 32 + ni * 8 + (lane & 3) * 2;
            *(float2*)(Sb + (size_t)gr * Tn + gc)       = make_float2(c[mi][ni][0], c[mi][ni][1]);
            *(float2*)(Sb + (size_t)(gr + 8) * Tn + gc) = make_float2(c[mi][ni][2], c[mi][ni][3]);
        }
    }
}

// ---------------------------------------------------------------------------
// K3: fused attention. 256 threads = 8 warps, 3 CTAs/SM (74.0KB smem).
// Phase A/softmax: warp = batch-pair x row-quad. PV: warp = batch.
// k-term precomputed (S init, prefetched). rel 3-deep cp.async pipeline.
// ---------------------------------------------------------------------------
#define RELBUF 16384                   // [tt8][hg4][v32] float4
#define Q_OFF  (3 * RELBUF)            // 49152: [b8][hg16][tt8] float4 = 16KB
#define PD_OFF (Q_OFF + 16384)         // 65536: [b8][r8][v32] float = 8KB
#define SC_OFF (PD_OFF + 8192)         // 73728: [b8][r8] float = 256B
#define ATTN_SMEM_BYTES (SC_OFF + 256) // 73984

__global__ __launch_bounds__(256, 3)
void attn_kernel(const float* __restrict__ rel)
{
    extern __shared__ float smf[];
    const uint32_t smem0 = smem_u32(smf);
    const uint32_t qu    = smem0 + Q_OFF;
    const uint32_t pdu   = smem0 + PD_OFF;

    const int tid  = threadIdx.x;
    const int w    = tid >> 5;
    const int lane = tid & 31;
    const int b0   = (w & 3) * 2;        // phase-A batch pair
    const int b1   = b0 + 1;
    const int rh4  = (w >> 2) << 2;      // phase-A row quad (0 or 4)
    const int t0   = blockIdx.x * TQ;
    const int vbase = blockIdx.y * VLEN;

    // ---- stage q: [b][hg][tt] float4 (published by first stage barrier) ----
    {
        float4* sq4 = (float4*)(smf + (Q_OFF >> 2));
        for (int idx = tid; idx < 1024; idx += 256) {
            int tt = idx & 7, hg = (idx >> 3) & 15, b = idx >> 7;
            sq4[(b * 16 + hg) * 8 + tt] =
                *(const float4*)(g_q + ((size_t)b * Tn + t0 + tt) * HSn + hg * 4);
        }
    }

    // ---- rel cp.async chunk bases (4 chunks/thread; c adds 2 to tt) ----
    const float* rsrc0 = rel + ((size_t)(t0 + (tid >> 7)) * Tn + vbase + (tid & 31)) * HSn
                             + ((tid >> 5) & 3) * 4;
    const uint32_t rdst0 = smem0 +
        (uint32_t)(((((tid >> 7) * 4 + ((tid >> 5) & 3)) * 32) + (tid & 31)) << 4);

    float m[2][4], l[2][4];
#pragma unroll
    for (int bi = 0; bi < 2; ++bi)
#pragma unroll
        for (int r = 0; r < 4; ++r) { m[bi][r] = -1e30f; l[bi][r] = 0.f; }

    ull oa2[8];                                    // PV: batch w, rows 0..7
#pragma unroll
    for (int r = 0; r < 8; ++r) oa2[r] = 0ull;

    const float* vb = g_v + (size_t)w * Tn * HSn;  // PV batch = w

    // ---- prologue: commit rel(0), rel(1); prefetch S for tile 0 ----
#pragma unroll
    for (int c = 0; c < 4; ++c)
        cp_async16(rdst0 + c * 4096, rsrc0 + (size_t)c * 262144);
    CP_COMMIT();
#pragma unroll
    for (int c = 0; c < 4; ++c)
        cp_async16(rdst0 + RELBUF + c * 4096, rsrc0 + (size_t)c * 262144 + 16);
    CP_COMMIT();

    float sf[2][4];
#pragma unroll
    for (int bi = 0; bi < 2; ++bi)
#pragma unroll
        for (int r = 0; r < 4; ++r)
            sf[bi][r] = __ldg(g_s + ((size_t)(b0 + bi) * Tn + t0 + rh4 + r) * Tn
                              + vbase + lane);

    ull s2h[2][4];
    for (int s = 0; s < NSTG; ++s) {
        CP_WAIT(1);               // rel(s) ready (rel(s+1) may be pending)
        __syncthreads();          // publish stage s; prove stage s-1 reads done

        if (s + 2 < NSTG) {
            const int s2 = s + 2;
            const float* sp = rsrc0 + (size_t)(s2 >> 2) * 2048 + (s2 & 3) * 16;
            uint32_t dp = rdst0 + (uint32_t)((s2 % 3) * RELBUF);
#pragma unroll
            for (int c = 0; c < 4; ++c)
                cp_async16(dp + c * 4096, sp + (size_t)c * 262144);
        }
        CP_COMMIT();

        const int tile = s >> 2, hq = s & 3;
        const int v0g  = vbase + tile * VT;
        const uint32_t relb = smem0 + (uint32_t)((s % 3) * RELBUF);

        if (hq == 0) {
            // init scores from precomputed S, then prefetch next tile's S
#pragma unroll
            for (int bi = 0; bi < 2; ++bi)
#pragma unroll
                for (int r = 0; r < 4; ++r) s2h[bi][r] = pack2(sf[bi][r], 0.f);
            if (tile + 1 < NTILE) {
#pragma unroll
                for (int bi = 0; bi < 2; ++bi)
#pragma unroll
                    for (int r = 0; r < 4; ++r)
                        sf[bi][r] = __ldg(g_s + ((size_t)(b0 + bi) * Tn + t0 + rh4 + r) * Tn
                                          + v0g + VT + lane);
            }
        }

        // ---- Phase A: rel-term only, packed h-pairs ----
#pragma unroll
        for (int hg = 0; hg < 4; ++hg) {
            const int hgg = hq * 4 + hg;
            const uint32_t qb0 = qu + (uint32_t)((((b0 * 16 + hgg) * 8) + rh4) << 4);
            const uint32_t qb1 = qu + (uint32_t)((((b1 * 16 + hgg) * 8) + rh4) << 4);
#pragma unroll
            for (int r = 0; r < 4; ++r) {
                ull r2a, r2b;
                lds_v2(r2a, r2b, relb + (uint32_t)(((((rh4 + r) * 4 + hg) * 32) + lane) << 4));
                ull q0a, q0b, q1a, q1b;
                lds_v2(q0a, q0b, qb0 + (uint32_t)(r << 4));
                lds_v2(q1a, q1b, qb1 + (uint32_t)(r << 4));
                s2h[0][r] = fma2(q0a, r2a, s2h[0][r]);
                s2h[0][r] = fma2(q0b, r2b, s2h[0][r]);
                s2h[1][r] = fma2(q1a, r2a, s2h[1][r]);
                s2h[1][r] = fma2(q1b, r2b, s2h[1][r]);
            }
        }

        if (hq == QPT - 1) {
            // ---- Phase B: online softmax ----
#pragma unroll
            for (int bi = 0; bi < 2; ++bi) {
                const int bb = b0 + bi;
#pragma unroll
                for (int r = 0; r < 4; ++r) {
                    float xa, xb;
                    unpack2(xa, xb, s2h[bi][r]);
                    float sv = xa + xb;
                    float mt = sv;
#pragma unroll
                    for (int o = 16; o > 0; o >>= 1)
                        mt = fmaxf(mt, __shfl_xor_sync(0xffffffffu, mt, o));
                    float mn = fmaxf(m[bi][r], mt);
                    float sc = __expf(m[bi][r] - mn);
                    float p  = __expf(sv - mn);
                    m[bi][r] = mn;
                    l[bi][r] = l[bi][r] * sc + p;
                    sts_f32(pdu + (uint32_t)((((bb * 8 + rh4 + r) * 32) + lane) * 4), p);
                    if (lane == 0) smf[(SC_OFF >> 2) + bb * 8 + rh4 + r] = sc;
                }
            }
            __syncthreads();      // publish p + sc to the PV warps

            // ---- Phase C: PV. Warp = batch w, rows 0..7, v read ONCE per CTA ----
#pragma unroll
            for (int r = 0; r < 8; ++r) {
                float scr = smf[(SC_OFF >> 2) + w * 8 + r];
                oa2[r] = mul2(oa2[r], pack2(scr, scr));
            }
            ull vc0, vc1, vn0, vn1;
            vc0 = ldg64(vb + (size_t)(v0g)     * HSn + 2 * lane);
            vc1 = ldg64(vb + (size_t)(v0g + 1) * HSn + 2 * lane);
#pragma unroll
            for (int vq = 0; vq < VT; vq += 2) {
                if (vq < VT - 2) {
                    vn0 = ldg64(vb + (size_t)(v0g + vq + 2) * HSn + 2 * lane);
                    vn1 = ldg64(vb + (size_t)(v0g + vq + 3) * HSn + 2 * lane);
                }
#pragma unroll
                for (int r = 0; r < 8; ++r) {
                    float p0, p1;
                    unpack2(p0, p1, lds64(pdu + (uint32_t)((((w * 8 + r) * 32) + vq) * 4)));
                    oa2[r] = fma2(pack2(p0, p0), vc0, oa2[r]);
                    oa2[r] = fma2(pack2(p1, p1), vc1, oa2[r]);
                }
                vc0 = vn0; vc1 = vn1;
            }
        }
    }

    // ---- write unnormalized partials ----
    const int sidx = blockIdx.y;
#pragma unroll
    for (int r = 0; r < 8; ++r) {
        int row = w * Tn + t0 + r;
        float o0, o1;
        unpack2(o0, o1, oa2[r]);
        ((float2*)(g_po[sidx] + (size_t)row * HSn))[lane] = make_float2(o0, o1);
    }
#pragma unroll
    for (int bi = 0; bi < 2; ++bi) {
        const int bb = b0 + bi;
#pragma unroll
        for (int r = 0; r < 4; ++r) {
            float lt = l[bi][r];
#pragma unroll
            for (int o = 16; o > 0; o >>= 1)
                lt += __shfl_xor_sync(0xffffffffu, lt, o);
            if (lane == 0) {
                int row = bb * Tn + t0 + rh4 + r;
                g_pm[sidx][row] = m[bi][r];
                g_pl[sidx][row] = lt;
            }
        }
    }
}

// ---------------------------------------------------------------------------
// K4: merge SPLIT partials -> normalized output (float4-vectorized)
// ---------------------------------------------------------------------------
__global__ __launch_bounds__(256)
void merge_kernel(float* __restrict__ out)
{
    int idx = blockIdx.x * 256 + threadIdx.x;   // over (B*T*HS)/4
    int row = idx >> 4;
    float M = g_pm[0][row];
#pragma unroll
    for (int s = 1; s < SPLIT; ++s) M = fmaxf(M, g_pm[s][row]);
    float denom = 0.f;
    float4 acc = make_float4(0.f, 0.f, 0.f, 0.f);
#pragma unroll
    for (int s = 0; s < SPLIT; ++s) {
        float a = __expf(g_pm[s][row] - M);
        denom += a * g_pl[s][row];
        float4 p = ((const float4*)g_po[s])[idx];
        acc.x += a * p.x; acc.y += a * p.y; acc.z += a * p.z; acc.w += a * p.w;
    }
    float inv = 1.0f / denom;
    ((float4*)out)[idx] = make_float4(acc.x * inv, acc.y * inv, acc.z * inv, acc.w * inv);
}

// ---------------------------------------------------------------------------
extern "C" void kernel_launch(void* const* d_in, const int* in_sizes, int n_in,
                              void* d_out, int out_size)
{
    const float* x   = (const float*)d_in[0];
    const float* Wk  = (const float*)d_in[1];
    const float* bk  = (const float*)d_in[2];
    const float* Wq  = (const float*)d_in[3];
    const float* bq  = (const float*)d_in[4];
    const float* Wv  = (const float*)d_in[5];
    const float* bv  = (const float*)d_in[6];
    const float* rel = (const float*)d_in[7];
    float* out = (float*)d_out;

    cudaFuncSetAttribute(attn_kernel,
                         cudaFuncAttributeMaxDynamicSharedMemorySize, ATTN_SMEM_BYTES);
    cudaFuncSetAttribute(qk_gemm_kernel,
                         cudaFuncAttributeMaxDynamicSharedMemorySize, GS_TOTAL);

    float* d_s;
    cudaGetSymbolAddress((void**)&d_s, g_s);

    proj_kernel<<<(Bn * Tn) / 32, 256>>>(x, Wk, bk, Wq, bq, Wv, bv);          // idx 0
    qk_gemm_kernel<<<dim3(Tn / GM, Tn / GN, Bn), 256, GS_TOTAL>>>(d_s);       // idx 1
    prof_pad_kernel<<<1, 32>>>(&g_pl[0][0]);                                  // idx 2
    attn_kernel<<<dim3(Tn / TQ, SPLIT), 256, ATTN_SMEM_BYTES>>>(rel);         // idx 3 (captured)
    merge_kernel<<<(Bn * Tn * HSn) / 1024, 256>>>(out);                       // idx 4

    (void)in_sizes; (void)n_in; (void)out_size;
}

// round 14
// speedup vs baseline: 1.1747x; 1.1747x over previous
#include <cuda_runtime.h>
#include <cuda_bf16.h>
#include <cstdint>
#include <cstddef>

typedef unsigned long long ull;

#define Bn 8
#define Tn 2048
#define Dn 1024
#define HSn 64
#define TQ 8
#define VT 32
#define SPLIT 8
#define VLEN (Tn / SPLIT)          // 256
#define NTILE (VLEN / VT)          // 8
#define QPT 4                      // h-quarter stages per tile
#define NSTG (NTILE * QPT)         // 32

// Scratch (allocation-free rule: __device__ globals)
__device__ float          g_q [(size_t)Bn * Tn * HSn];   // [b][t][h] fp32 (rel term)
__device__ __nv_bfloat16  g_qh[(size_t)Bn * Tn * HSn];   // hi(8q)
__device__ __nv_bfloat16  g_ql[(size_t)Bn * Tn * HSn];   // lo(8q)
__device__ __nv_bfloat16  g_kh[(size_t)Bn * Tn * HSn];   // hi(k)
__device__ __nv_bfloat16  g_kl[(size_t)Bn * Tn * HSn];   // lo(k)
__device__ float          g_v [(size_t)Bn * Tn * HSn];   // [b][t][h]
__device__ float          g_s [(size_t)Bn * Tn * Tn];    // S = 8 q k^T  [b][t][v]
__device__ float g_po[SPLIT][(size_t)Bn * Tn * HSn];
__device__ float g_pm[SPLIT][Bn * Tn];
__device__ float g_pl[SPLIT][Bn * Tn];

// ---- f32x2 + wide-load helpers --------------------------------------------
__device__ __forceinline__ ull pack2(float a, float b) {
    ull r; asm("mov.b64 %0, {%1, %2};" : "=l"(r) : "f"(a), "f"(b)); return r;
}
__device__ __forceinline__ ull mul2(ull a, ull b) {
    ull r; asm("mul.rn.f32x2 %0, %1, %2;" : "=l"(r) : "l"(a), "l"(b)); return r;
}
__device__ __forceinline__ ull fma2(ull a, ull b, ull c) {
    ull r; asm("fma.rn.f32x2 %0, %1, %2, %3;" : "=l"(r) : "l"(a), "l"(b), "l"(c)); return r;
}
__device__ __forceinline__ void unpack2(float& lo, float& hi, ull v) {
    asm("mov.b64 {%0, %1}, %2;" : "=f"(lo), "=f"(hi) : "l"(v));
}
__device__ __forceinline__ void lds_v2(ull& a, ull& b, uint32_t addr) {
    asm volatile("ld.shared.v2.b64 {%0, %1}, [%2];" : "=l"(a), "=l"(b) : "r"(addr));
}
__device__ __forceinline__ ull lds64(uint32_t addr) {
    ull r; asm volatile("ld.shared.b64 %0, [%1];" : "=l"(r) : "r"(addr)); return r;
}
__device__ __forceinline__ ull ldg64(const void* p) {
    ull r; asm volatile("ld.global.nc.b64 %0, [%1];" : "=l"(r) : "l"(p)); return r;
}
__device__ __forceinline__ void sts_f32(uint32_t addr, float p) {
    asm volatile("st.shared.f32 [%0], %1;" :: "r"(addr), "f"(p) : "memory");
}
__device__ __forceinline__ void cp_async16(uint32_t dst, const void* src) {
    asm volatile("cp.async.cg.shared.global [%0], [%1], 16;" :: "r"(dst), "l"(src) : "memory");
}
#define CP_COMMIT()  asm volatile("cp.async.commit_group;" ::: "memory")
#define CP_WAIT(n)   asm volatile("cp.async.wait_group %0;" :: "n"(n) : "memory")

__device__ __forceinline__ uint32_t smem_u32(const void* p) {
    return (uint32_t)__cvta_generic_to_shared(p);
}

// ---------------------------------------------------------------------------
// K0: profiler pad (keeps attn at captured launch idx 3).
// ---------------------------------------------------------------------------
__global__ void prof_pad_kernel(float* __restrict__ dst)
{
    if (threadIdx.x == 0) dst[0] = -1e30f;   // overwritten before use
}

// ---------------------------------------------------------------------------
// K1: fused QKV projection (R5 core — measured best ~306us) + bf16 splits.
// ---------------------------------------------------------------------------
__global__ __launch_bounds__(256, 3)
void proj_kernel(const float* __restrict__ x,
                 const float* __restrict__ Wk, const float* __restrict__ bk,
                 const float* __restrict__ Wq, const float* __restrict__ bq,
                 const float* __restrict__ Wv, const float* __restrict__ bv)
{
    __shared__ float xsT[64 * 36];     // [k][tok]
    __shared__ float ws[64][193];      // [k][col]

    const int tid  = threadIdx.x;
    const int tok0 = blockIdx.x * 32;
    const int cl   = tid & 31;
    const int tr   = (tid >> 5) << 2;

    const uint32_t xsT_u = smem_u32(xsT);

    ull acc2[2][6];
#pragma unroll
    for (int i = 0; i < 2; ++i)
#pragma unroll
        for (int j = 0; j < 6; ++j) acc2[i][j] = 0ull;

    for (int k0 = 0; k0 < Dn; k0 += 64) {
        __syncthreads();
        for (int idx = tid; idx < 32 * 64; idx += 256) {
            int k = idx & 63, tk = idx >> 6;
            xsT[k * 36 + tk] = x[(size_t)(tok0 + tk) * Dn + k0 + k];
        }
        for (int idx = tid; idx < 192 * 64; idx += 256) {
            int k = idx & 63, col = idx >> 6;
            const float* Wsrc = (col < 64) ? Wk : ((col < 128) ? Wq : Wv);
            ws[k][col] = Wsrc[(size_t)(col & 63) * Dn + k0 + k];
        }
        __syncthreads();

#pragma unroll 8
        for (int k = 0; k < 64; ++k) {
            ull x2a, x2b;
            lds_v2(x2a, x2b, xsT_u + (uint32_t)(k * 36 + tr) * 4u);
#pragma unroll
            for (int j = 0; j < 6; ++j) {
                float wv = ws[k][cl + 32 * j];
                ull wd = pack2(wv, wv);
                acc2[0][j] = fma2(x2a, wd, acc2[0][j]);
                acc2[1][j] = fma2(x2b, wd, acc2[1][j]);
            }
        }
    }

#pragma unroll
    for (int j = 0; j < 6; ++j) {
        float a[4];
        unpack2(a[0], a[1], acc2[0][j]);
        unpack2(a[2], a[3], acc2[1][j]);
        int col = cl + 32 * j;
        int h = col & 63;
#pragma unroll
        for (int i = 0; i < 4; ++i) {
            int tokg = tok0 + tr + i;
            size_t off = (size_t)tokg * HSn + h;
            if (col < 64) {
                float r = a[i] + bk[h];
                __nv_bfloat16 rh = __float2bfloat16(r);
                g_kh[off] = rh;
                g_kl[off] = __float2bfloat16(r - __bfloat162float(rh));
            } else if (col < 128) {
                float qf = a[i] + bq[h];
                g_q[off] = qf;                         // fp32 (rel term)
                float q8 = 8.0f * qf;                  // fold sqrt(HS)=8
                __nv_bfloat16 qh8 = __float2bfloat16(q8);
                g_qh[off] = qh8;
                g_ql[off] = __float2bfloat16(q8 - __bfloat162float(qh8));
            } else {
                g_v[off] = a[i] + bv[h];
            }
        }
    }
}

// ---------------------------------------------------------------------------
// K2: S = 8 q k^T via warp-level HMMA (mma.sync m16n8k16 bf16), 3-pass split.
// Grid (16, 16, 8). CTA: 256 thr = 8 warps, tile M=128 x N=128, K=64.
// (unchanged from R13 — verified rel_err 2.8e-5)
// ---------------------------------------------------------------------------
#define GM 128
#define GN 128
#define SW128(off) ((off) ^ (((off) >> 3) & 0x70))
#define GS_AH 0
#define GS_AL 16384
#define GS_BH 32768
#define GS_BL 49152
#define GS_TOTAL 65536

__device__ __forceinline__ void ldmatrix_x4(uint32_t& r0, uint32_t& r1,
                                            uint32_t& r2, uint32_t& r3, uint32_t addr)
{
    asm volatile("ldmatrix.sync.aligned.m8n8.x4.shared.b16 {%0,%1,%2,%3}, [%4];"
                 : "=r"(r0), "=r"(r1), "=r"(r2), "=r"(r3) : "r"(addr));
}
__device__ __forceinline__ void mma_16816(float* c, const uint32_t* a,
                                          uint32_t b0, uint32_t b1)
{
    asm volatile(
        "mma.sync.aligned.m16n8k16.row.col.f32.bf16.bf16.f32 "
        "{%0,%1,%2,%3}, {%4,%5,%6,%7}, {%8,%9}, {%0,%1,%2,%3};"
        : "+f"(c[0]), "+f"(c[1]), "+f"(c[2]), "+f"(c[3])
        : "r"(a[0]), "r"(a[1]), "r"(a[2]), "r"(a[3]), "r"(b0), "r"(b1));
}

__global__ __launch_bounds__(256, 2)
void qk_gemm_kernel(float* __restrict__ S)
{
    extern __shared__ char gsm[];
    const uint32_t sm0 = smem_u32(gsm);
    const int tid  = threadIdx.x;
    const int wid  = tid >> 5;
    const int lane = tid & 31;
    const int t0   = blockIdx.x * GM;
    const int v0   = blockIdx.y * GN;
    const int b    = blockIdx.z;
    const int wm   = wid & 1;
    const int wn   = wid >> 1;

    const char* qh = (const char*)(g_qh + ((size_t)b * Tn + t0) * HSn);
    const char* ql = (const char*)(g_ql + ((size_t)b * Tn + t0) * HSn);
    const char* kh = (const char*)(g_kh + ((size_t)b * Tn + v0) * HSn);
    const char* kl = (const char*)(g_kl + ((size_t)b * Tn + v0) * HSn);
    for (int idx = tid; idx < GM * 8; idx += 256) {
        int row = idx >> 3, c16 = idx & 7;
        int src = row * 128 + c16 * 16;
        uint32_t off = SW128((uint32_t)src);
        *(uint4*)(gsm + GS_AH + off) = *(const uint4*)(qh + src);
        *(uint4*)(gsm + GS_AL + off) = *(const uint4*)(ql + src);
        *(uint4*)(gsm + GS_BH + off) = *(const uint4*)(kh + src);
        *(uint4*)(gsm + GS_BL + off) = *(const uint4*)(kl + src);
    }
    __syncthreads();

    float c[4][4][4];
#pragma unroll
    for (int mi = 0; mi < 4; ++mi)
#pragma unroll
        for (int ni = 0; ni < 4; ++ni)
#pragma unroll
            for (int e = 0; e < 4; ++e) c[mi][ni][e] = 0.f;

    const int ar = (lane & 7) + ((lane >> 3) & 1) * 8;
    const int ac = (lane >> 4) * 8;

#pragma unroll
    for (int pass = 0; pass < 3; ++pass) {
        const uint32_t abase = sm0 + ((pass == 2) ? GS_AL : GS_AH);
        const uint32_t bbase = sm0 + ((pass == 1) ? GS_BL : GS_BH);
#pragma unroll
        for (int ks = 0; ks < 4; ++ks) {
            uint32_t a[4][4];
#pragma unroll
            for (int mi = 0; mi < 4; ++mi) {
                uint32_t byte = (uint32_t)((wm * 64 + mi * 16 + ar) * 128
                                           + (ks * 16 + ac) * 2);
                ldmatrix_x4(a[mi][0], a[mi][1], a[mi][2], a[mi][3],
                            abase + SW128(byte));
            }
            uint32_t bf[4][2];
#pragma unroll
            for (int np = 0; np < 2; ++np) {
                uint32_t byte = (uint32_t)((wn * 32 + np * 16 + ar) * 128
                                           + (ks * 16 + ac) * 2);
                uint32_t r0, r1, r2, r3;
                ldmatrix_x4(r0, r1, r2, r3, bbase + SW128(byte));
                bf[2 * np][0] = r0; bf[2 * np + 1][0] = r1;
                bf[2 * np][1] = r2; bf[2 * np + 1][1] = r3;
            }
#pragma unroll
            for (int mi = 0; mi < 4; ++mi)
#pragma unroll
                for (int ni = 0; ni < 4; ++ni)
                    mma_16816(c[mi][ni], a[mi], bf[ni][0], bf[ni][1]);
        }
    }

    float* Sb = S + (size_t)b * Tn * Tn;
#pragma unroll
    for (int mi = 0; mi < 4; ++mi) {
#pragma unroll
        for (int ni = 0; ni < 4; ++ni) {
            int gr = t0 + wm * 64 + mi * 16 + (lane >> 2);
            int gc = v0 + wn * 32 + ni * 8 + (lane & 3) * 2;
            *(float2*)(Sb + (size_t)gr * Tn + gc)       = make_float2(c[mi][ni][0], c[mi][ni][1]);
            *(float2*)(Sb + (size_t)(gr + 8) * Tn + gc) = make_float2(c[mi][ni][2], c[mi][ni][3]);
        }
    }
}

// ---------------------------------------------------------------------------
// K3: fused attention. 256 threads = 8 warps, 3 CTAs/SM.
// R14: Phase A/softmax warp = ONE t-row x ALL 8 batches -> rel LDS
// multiplicity 4 -> 1. p stored [row][b][v]; sc [row][b]. PV: warp = batch.
// ---------------------------------------------------------------------------
#define RELBUF 16384                   // [tt8][hg4][v32] float4
#define Q_OFF  (3 * RELBUF)            // 49152: [b8][hg16][tt8] float4 = 16KB
#define PD_OFF (Q_OFF + 16384)         // 65536: [row8][b8][v32] float = 8KB
#define SC_OFF (PD_OFF + 8192)         // 73728: [row8][b8] float = 256B
#define ATTN_SMEM_BYTES (SC_OFF + 256) // 73984

__global__ __launch_bounds__(256, 3)
void attn_kernel(const float* __restrict__ rel)
{
    extern __shared__ float smf[];
    const uint32_t smem0 = smem_u32(smf);
    const uint32_t qu    = smem0 + Q_OFF;
    const uint32_t pdu   = smem0 + PD_OFF;

    const int tid  = threadIdx.x;
    const int w    = tid >> 5;           // phase A: row w ; PV: batch w
    const int lane = tid & 31;
    const int t0   = blockIdx.x * TQ;
    const int vbase = blockIdx.y * VLEN;

    // ---- stage q: [b][hg][tt] float4 (published by first stage barrier) ----
    {
        float4* sq4 = (float4*)(smf + (Q_OFF >> 2));
        for (int idx = tid; idx < 1024; idx += 256) {
            int tt = idx & 7, hg = (idx >> 3) & 15, b = idx >> 7;
            sq4[(b * 16 + hg) * 8 + tt] =
                *(const float4*)(g_q + ((size_t)b * Tn + t0 + tt) * HSn + hg * 4);
        }
    }

    // ---- rel cp.async chunk bases (4 chunks/thread; c adds 2 to tt) ----
    const float* rsrc0 = rel + ((size_t)(t0 + (tid >> 7)) * Tn + vbase + (tid & 31)) * HSn
                             + ((tid >> 5) & 3) * 4;
    const uint32_t rdst0 = smem0 +
        (uint32_t)(((((tid >> 7) * 4 + ((tid >> 5) & 3)) * 32) + (tid & 31)) << 4);

    float m[8], l[8];
#pragma unroll
    for (int b = 0; b < 8; ++b) { m[b] = -1e30f; l[b] = 0.f; }

    ull oa2[8];                                    // PV: batch w, rows 0..7
#pragma unroll
    for (int r = 0; r < 8; ++r) oa2[r] = 0ull;

    const float* vb = g_v + (size_t)w * Tn * HSn;  // PV batch = w
    const float* srow = g_s + (size_t)(t0 + w) * Tn;   // + b*Tn*Tn per batch

    // ---- prologue: commit rel(0), rel(1) ----
#pragma unroll
    for (int c = 0; c < 4; ++c)
        cp_async16(rdst0 + c * 4096, rsrc0 + (size_t)c * 262144);
    CP_COMMIT();
#pragma unroll
    for (int c = 0; c < 4; ++c)
        cp_async16(rdst0 + RELBUF + c * 4096, rsrc0 + (size_t)c * 262144 + 16);
    CP_COMMIT();

    ull s2h[8];                                    // phase A: batch accumulators
    for (int s = 0; s < NSTG; ++s) {
        CP_WAIT(1);               // rel(s) ready (rel(s+1) may be pending)
        __syncthreads();          // publish stage s; prove stage s-1 reads done

        if (s + 2 < NSTG) {
            const int s2 = s + 2;
            const float* sp = rsrc0 + (size_t)(s2 >> 2) * 2048 + (s2 & 3) * 16;
            uint32_t dp = rdst0 + (uint32_t)((s2 % 3) * RELBUF);
#pragma unroll
            for (int c = 0; c < 4; ++c)
                cp_async16(dp + c * 4096, sp + (size_t)c * 262144);
        }
        CP_COMMIT();

        const int tile = s >> 2, hq = s & 3;
        const int v0g  = vbase + tile * VT;
        const uint32_t relb = smem0 + (uint32_t)((s % 3) * RELBUF);

        if (hq == 0) {
            // init scores from precomputed S (one coalesced LDG per batch)
#pragma unroll
            for (int b = 0; b < 8; ++b)
                s2h[b] = pack2(__ldg(srow + (size_t)b * Tn * Tn + v0g + lane), 0.f);
        }

        // ---- Phase A: rel-term, warp = row w, 8 batches ----
#pragma unroll
        for (int hg = 0; hg < 4; ++hg) {
            ull r2a, r2b;
            lds_v2(r2a, r2b, relb + (uint32_t)((((w * 4 + hg) * 32) + lane) << 4));
            const int hgg = hq * 4 + hg;
            const uint32_t qb = qu + (uint32_t)(((hgg * 8) + w) << 4);
#pragma unroll
            for (int b = 0; b < 8; ++b) {
                ull q2a, q2b;
                lds_v2(q2a, q2b, qb + (uint32_t)((b * 16 * 8) << 4));  // [b][hgg][w]
                s2h[b] = fma2(q2a, r2a, s2h[b]);
                s2h[b] = fma2(q2b, r2b, s2h[b]);
            }
        }

        if (hq == QPT - 1) {
            // ---- Phase B: online softmax (warp owns row w, 8 batches) ----
#pragma unroll
            for (int b = 0; b < 8; ++b) {
                float xa, xb;
                unpack2(xa, xb, s2h[b]);
                float sv = xa + xb;
                float mt = sv;
#pragma unroll
                for (int o = 16; o > 0; o >>= 1)
                    mt = fmaxf(mt, __shfl_xor_sync(0xffffffffu, mt, o));
                float mn = fmaxf(m[b], mt);
                float sc = __expf(m[b] - mn);
                float p  = __expf(sv - mn);
                m[b] = mn;
                l[b] = l[b] * sc + p;
                sts_f32(pdu + (uint32_t)((((w * 8 + b) * 32) + lane) * 4), p);
                if (lane == 0) smf[(SC_OFF >> 2) + w * 8 + b] = sc;
            }
            __syncthreads();      // publish p + sc to the PV warps

            // ---- Phase C: PV. Warp = batch w, rows 0..7 ----
#pragma unroll
            for (int r = 0; r < 8; ++r) {
                float scr = smf[(SC_OFF >> 2) + r * 8 + w];
                oa2[r] = mul2(oa2[r], pack2(scr, scr));
            }
            ull vc0, vc1, vn0, vn1;
            vc0 = ldg64(vb + (size_t)(v0g)     * HSn + 2 * lane);
            vc1 = ldg64(vb + (size_t)(v0g + 1) * HSn + 2 * lane);
#pragma unroll
            for (int vq = 0; vq < VT; vq += 2) {
                if (vq < VT - 2) {
                    vn0 = ldg64(vb + (size_t)(v0g + vq + 2) * HSn + 2 * lane);
                    vn1 = ldg64(vb + (size_t)(v0g + vq + 3) * HSn + 2 * lane);
                }
#pragma unroll
                for (int r = 0; r < 8; ++r) {
                    float p0, p1;
                    unpack2(p0, p1, lds64(pdu + (uint32_t)((((r * 8 + w) * 32) + vq) * 4)));
                    oa2[r] = fma2(pack2(p0, p0), vc0, oa2[r]);
                    oa2[r] = fma2(pack2(p1, p1), vc1, oa2[r]);
                }
                vc0 = vn0; vc1 = vn1;
            }
        }
    }

    // ---- write unnormalized partials ----
    const int sidx = blockIdx.y;
#pragma unroll
    for (int r = 0; r < 8; ++r) {
        int row = w * Tn + t0 + r;       // PV warp = batch w
        float o0, o1;
        unpack2(o0, o1, oa2[r]);
        ((float2*)(g_po[sidx] + (size_t)row * HSn))[lane] = make_float2(o0, o1);
    }
#pragma unroll
    for (int b = 0; b < 8; ++b) {        // softmax warp = row w
        float lt = l[b];
#pragma unroll
        for (int o = 16; o > 0; o >>= 1)
            lt += __shfl_xor_sync(0xffffffffu, lt, o);
        if (lane == 0) {
            int row = b * Tn + t0 + w;
            g_pm[sidx][row] = m[b];
            g_pl[sidx][row] = lt;
        }
    }
}

// ---------------------------------------------------------------------------
// K4: merge SPLIT partials -> normalized output (float4-vectorized)
// ---------------------------------------------------------------------------
__global__ __launch_bounds__(256)
void merge_kernel(float* __restrict__ out)
{
    int idx = blockIdx.x * 256 + threadIdx.x;   // over (B*T*HS)/4
    int row = idx >> 4;
    float M = g_pm[0][row];
#pragma unroll
    for (int s = 1; s < SPLIT; ++s) M = fmaxf(M, g_pm[s][row]);
    float denom = 0.f;
    float4 acc = make_float4(0.f, 0.f, 0.f, 0.f);
#pragma unroll
    for (int s = 0; s < SPLIT; ++s) {
        float a = __expf(g_pm[s][row] - M);
        denom += a * g_pl[s][row];
        float4 p = ((const float4*)g_po[s])[idx];
        acc.x += a * p.x; acc.y += a * p.y; acc.z += a * p.z; acc.w += a * p.w;
    }
    float inv = 1.0f / denom;
    ((float4*)out)[idx] = make_float4(acc.x * inv, acc.y * inv, acc.z * inv, acc.w * inv);
}

// ---------------------------------------------------------------------------
extern "C" void kernel_launch(void* const* d_in, const int* in_sizes, int n_in,
                              void* d_out, int out_size)
{
    const float* x   = (const float*)d_in[0];
    const float* Wk  = (const float*)d_in[1];
    const float* bk  = (const float*)d_in[2];
    const float* Wq  = (const float*)d_in[3];
    const float* bq  = (const float*)d_in[4];
    const float* Wv  = (const float*)d_in[5];
    const float* bv  = (const float*)d_in[6];
    const float* rel = (const float*)d_in[7];
    float* out = (float*)d_out;

    cudaFuncSetAttribute(attn_kernel,
                         cudaFuncAttributeMaxDynamicSharedMemorySize, ATTN_SMEM_BYTES);
    cudaFuncSetAttribute(qk_gemm_kernel,
                         cudaFuncAttributeMaxDynamicSharedMemorySize, GS_TOTAL);

    float* d_s;
    cudaGetSymbolAddress((void**)&d_s, g_s);

    proj_kernel<<<(Bn * Tn) / 32, 256>>>(x, Wk, bk, Wq, bq, Wv, bv);          // idx 0
    qk_gemm_kernel<<<dim3(Tn / GM, Tn / GN, Bn), 256, GS_TOTAL>>>(d_s);       // idx 1
    prof_pad_kernel<<<1, 32>>>(&g_pl[0][0]);                                  // idx 2
    attn_kernel<<<dim3(Tn / TQ, SPLIT), 256, ATTN_SMEM_BYTES>>>(rel);         // idx 3 (captured)
    merge_kernel<<<(Bn * Tn * HSn) / 1024, 256>>>(out);                       // idx 4

    (void)in_sizes; (void)n_in; (void)out_size;
}

// round 15
// speedup vs baseline: 1.5041x; 1.2803x over previous
#include <cuda_runtime.h>
#include <cuda_bf16.h>
#include <cstdint>
#include <cstddef>

typedef unsigned long long ull;

#define Bn 8
#define Tn 2048
#define Dn 1024
#define HSn 64
#define TQ 8
#define VT 32
#define SPLIT 8
#define VLEN (Tn / SPLIT)          // 256
#define NTILE (VLEN / VT)          // 8
#define QPT 4                      // h-quarter stages per tile
#define NSTG (NTILE * QPT)         // 32

// Scratch (allocation-free rule: __device__ globals)
__device__ float          g_q [(size_t)Bn * Tn * HSn];   // [b][t][h] fp32 (rel term)
__device__ __nv_bfloat16  g_qh[(size_t)Bn * Tn * HSn];   // hi(8q)
__device__ __nv_bfloat16  g_ql[(size_t)Bn * Tn * HSn];   // lo(8q)
__device__ __nv_bfloat16  g_kh[(size_t)Bn * Tn * HSn];   // hi(k)
__device__ __nv_bfloat16  g_kl[(size_t)Bn * Tn * HSn];   // lo(k)
__device__ float          g_v [(size_t)Bn * Tn * HSn];   // [b][t][h]
__device__ float          g_s [(size_t)Bn * Tn * Tn];    // S = 8 q k^T  [b][t][v]
__device__ __nv_bfloat16  g_xh[(size_t)Bn * Tn * Dn];    // hi(x)
__device__ __nv_bfloat16  g_xl[(size_t)Bn * Tn * Dn];    // lo(x)
__device__ __nv_bfloat16  g_wh[(size_t)192 * Dn];        // hi(W) rows: [Wk;Wq;Wv]
__device__ __nv_bfloat16  g_wl[(size_t)192 * Dn];        // lo(W)
__device__ float g_po[SPLIT][(size_t)Bn * Tn * HSn];
__device__ float g_pm[SPLIT][Bn * Tn];
__device__ float g_pl[SPLIT][Bn * Tn];

// ---- f32x2 + wide-load helpers --------------------------------------------
__device__ __forceinline__ ull pack2(float a, float b) {
    ull r; asm("mov.b64 %0, {%1, %2};" : "=l"(r) : "f"(a), "f"(b)); return r;
}
__device__ __forceinline__ ull mul2(ull a, ull b) {
    ull r; asm("mul.rn.f32x2 %0, %1, %2;" : "=l"(r) : "l"(a), "l"(b)); return r;
}
__device__ __forceinline__ ull fma2(ull a, ull b, ull c) {
    ull r; asm("fma.rn.f32x2 %0, %1, %2, %3;" : "=l"(r) : "l"(a), "l"(b), "l"(c)); return r;
}
__device__ __forceinline__ void unpack2(float& lo, float& hi, ull v) {
    asm("mov.b64 {%0, %1}, %2;" : "=f"(lo), "=f"(hi) : "l"(v));
}
__device__ __forceinline__ void lds_v2(ull& a, ull& b, uint32_t addr) {
    asm volatile("ld.shared.v2.b64 {%0, %1}, [%2];" : "=l"(a), "=l"(b) : "r"(addr));
}
__device__ __forceinline__ ull lds64(uint32_t addr) {
    ull r; asm volatile("ld.shared.b64 %0, [%1];" : "=l"(r) : "r"(addr)); return r;
}
__device__ __forceinline__ ull ldg64(const void* p) {
    ull r; asm volatile("ld.global.nc.b64 %0, [%1];" : "=l"(r) : "l"(p)); return r;
}
__device__ __forceinline__ void sts_f32(uint32_t addr, float p) {
    asm volatile("st.shared.f32 [%0], %1;" :: "r"(addr), "f"(p) : "memory");
}
__device__ __forceinline__ void cp_async16(uint32_t dst, const void* src) {
    asm volatile("cp.async.cg.shared.global [%0], [%1], 16;" :: "r"(dst), "l"(src) : "memory");
}
#define CP_COMMIT()  asm volatile("cp.async.commit_group;" ::: "memory")
#define CP_WAIT(n)   asm volatile("cp.async.wait_group %0;" :: "n"(n) : "memory")

__device__ __forceinline__ uint32_t smem_u32(const void* p) {
    return (uint32_t)__cvta_generic_to_shared(p);
}

#define SW128(off) ((off) ^ (((off) >> 3) & 0x70))

__device__ __forceinline__ void ldmatrix_x4(uint32_t& r0, uint32_t& r1,
                                            uint32_t& r2, uint32_t& r3, uint32_t addr)
{
    asm volatile("ldmatrix.sync.aligned.m8n8.x4.shared.b16 {%0,%1,%2,%3}, [%4];"
                 : "=r"(r0), "=r"(r1), "=r"(r2), "=r"(r3) : "r"(addr));
}
__device__ __forceinline__ void mma_16816(float* c, const uint32_t* a,
                                          uint32_t b0, uint32_t b1)
{
    asm volatile(
        "mma.sync.aligned.m16n8k16.row.col.f32.bf16.bf16.f32 "
        "{%0,%1,%2,%3}, {%4,%5,%6,%7}, {%8,%9}, {%0,%1,%2,%3};"
        : "+f"(c[0]), "+f"(c[1]), "+f"(c[2]), "+f"(c[3])
        : "r"(a[0]), "r"(a[1]), "r"(a[2]), "r"(a[3]), "r"(b0), "r"(b1));
}

// ---------------------------------------------------------------------------
// K0: xcvt — split x into bf16 hi/lo; pack+split W rows [Wk;Wq;Wv].
// Grid 16384: 4 elements/thread via float4.
// ---------------------------------------------------------------------------
__global__ __launch_bounds__(256)
void xcvt_kernel(const float* __restrict__ x,
                 const float* __restrict__ Wk,
                 const float* __restrict__ Wq,
                 const float* __restrict__ Wv)
{
    size_t i4 = (size_t)blockIdx.x * 256 + threadIdx.x;   // over 16.7M/4
    float4 xv = ((const float4*)x)[i4];
    const float* e = (const float*)&xv;
    __nv_bfloat162* xh2 = (__nv_bfloat162*)g_xh;
    __nv_bfloat162* xl2 = (__nv_bfloat162*)g_xl;
    __nv_bfloat16 h[4], lo[4];
#pragma unroll
    for (int j = 0; j < 4; ++j) {
        h[j]  = __float2bfloat16(e[j]);
        lo[j] = __float2bfloat16(e[j] - __bfloat162float(h[j]));
    }
    xh2[2 * i4]     = __nv_bfloat162(h[0], h[1]);
    xh2[2 * i4 + 1] = __nv_bfloat162(h[2], h[3]);
    xl2[2 * i4]     = __nv_bfloat162(lo[0], lo[1]);
    xl2[2 * i4 + 1] = __nv_bfloat162(lo[2], lo[3]);

    if (i4 < 192 * Dn / 4) {
        size_t base = i4 * 4;
        int col = (int)(base >> 10);
        int k   = (int)(base & 1023);
        const float* Wsrc = (col < 64) ? (Wk + (size_t)col * Dn)
                          : (col < 128) ? (Wq + (size_t)(col - 64) * Dn)
                                        : (Wv + (size_t)(col - 128) * Dn);
        float4 wv = *(const float4*)(Wsrc + k);
        const float* we = (const float*)&wv;
        __nv_bfloat162* wh2 = (__nv_bfloat162*)g_wh;
        __nv_bfloat162* wl2 = (__nv_bfloat162*)g_wl;
        __nv_bfloat16 wh[4], wl[4];
#pragma unroll
        for (int j = 0; j < 4; ++j) {
            wh[j] = __float2bfloat16(we[j]);
            wl[j] = __float2bfloat16(we[j] - __bfloat162float(wh[j]));
        }
        wh2[2 * i4]     = __nv_bfloat162(wh[0], wh[1]);
        wh2[2 * i4 + 1] = __nv_bfloat162(wh[2], wh[3]);
        wl2[2 * i4]     = __nv_bfloat162(wl[0], wl[1]);
        wl2[2 * i4 + 1] = __nv_bfloat162(wl[2], wl[3]);
    }
}

// ---------------------------------------------------------------------------
// K1: proj via HMMA bf16x3-split. Grid 256 (M=64 tile), N=192, K=1024.
// 8 warps: wm = wid&1 (32 rows), wn = wid>>1 (48 cols = 6 n-frags).
// K streamed in 16 chunks of 64, single-buffered cp.async (2 CTAs/SM hide it).
// Epilogue: +bias, fan out to g_q / g_qh,g_ql (8q split) / g_kh,g_kl / g_v.
// ---------------------------------------------------------------------------
#define PS_XH 0
#define PS_XL 8192
#define PS_WH 16384
#define PS_WL 40960
#define PS_TOTAL 65536

__global__ __launch_bounds__(256, 2)
void proj_hmma_kernel(const float* __restrict__ bk,
                      const float* __restrict__ bq,
                      const float* __restrict__ bv)
{
    extern __shared__ char psm[];
    const uint32_t sm0 = smem_u32(psm);
    const int tid  = threadIdx.x;
    const int wid  = tid >> 5;
    const int lane = tid & 31;
    const int t0   = blockIdx.x * 64;
    const int wm   = wid & 1;
    const int wn   = wid >> 1;

    float c[2][6][4];
#pragma unroll
    for (int mi = 0; mi < 2; ++mi)
#pragma unroll
        for (int ni = 0; ni < 6; ++ni)
#pragma unroll
            for (int e = 0; e < 4; ++e) c[mi][ni][e] = 0.f;

    const int ar = (lane & 7) + ((lane >> 3) & 1) * 8;
    const int ac = (lane >> 4) * 8;

    for (int ck = 0; ck < 16; ++ck) {
        __syncthreads();            // previous chunk compute done
        // stage A: 64 rows x 128B (xh, xl)
        for (int i = tid; i < 512; i += 256) {
            int row = i >> 3, c16 = i & 7;
            uint32_t off = SW128((uint32_t)(row * 128 + c16 * 16));
            const char* sxh = (const char*)(g_xh + ((size_t)(t0 + row)) * Dn + ck * 64);
            const char* sxl = (const char*)(g_xl + ((size_t)(t0 + row)) * Dn + ck * 64);
            cp_async16(sm0 + PS_XH + off, sxh + c16 * 16);
            cp_async16(sm0 + PS_XL + off, sxl + c16 * 16);
        }
        // stage B: 192 rows x 128B (wh, wl)
        for (int i = tid; i < 1536; i += 256) {
            int row = i >> 3, c16 = i & 7;
            uint32_t off = SW128((uint32_t)(row * 128 + c16 * 16));
            const char* swh = (const char*)(g_wh + (size_t)row * Dn + ck * 64);
            const char* swl = (const char*)(g_wl + (size_t)row * Dn + ck * 64);
            cp_async16(sm0 + PS_WH + off, swh + c16 * 16);
            cp_async16(sm0 + PS_WL + off, swl + c16 * 16);
        }
        CP_COMMIT();
        CP_WAIT(0);
        __syncthreads();

#pragma unroll
        for (int pass = 0; pass < 3; ++pass) {
            const uint32_t abase = sm0 + ((pass == 2) ? PS_XL : PS_XH);
            const uint32_t bbase = sm0 + ((pass == 1) ? PS_WL : PS_WH);
#pragma unroll
            for (int ks = 0; ks < 4; ++ks) {
                uint32_t a[2][4];
#pragma unroll
                for (int mi = 0; mi < 2; ++mi) {
                    uint32_t byte = (uint32_t)((wm * 32 + mi * 16 + ar) * 128
                                               + (ks * 16 + ac) * 2);
                    ldmatrix_x4(a[mi][0], a[mi][1], a[mi][2], a[mi][3],
                                abase + SW128(byte));
                }
                uint32_t bf[6][2];
#pragma unroll
                for (int np = 0; np < 3; ++np) {
                    uint32_t byte = (uint32_t)((wn * 48 + np * 16 + ar) * 128
                                               + (ks * 16 + ac) * 2);
                    uint32_t r0, r1, r2, r3;
                    ldmatrix_x4(r0, r1, r2, r3, bbase + SW128(byte));
                    bf[2 * np][0] = r0; bf[2 * np + 1][0] = r1;
                    bf[2 * np][1] = r2; bf[2 * np + 1][1] = r3;
                }
#pragma unroll
                for (int mi = 0; mi < 2; ++mi)
#pragma unroll
                    for (int ni = 0; ni < 6; ++ni)
                        mma_16816(c[mi][ni], a[mi], bf[ni][0], bf[ni][1]);
            }
        }
    }

    // ---- epilogue: bias + fan-out ----
#pragma unroll
    for (int mi = 0; mi < 2; ++mi) {
#pragma unroll
        for (int ni = 0; ni < 6; ++ni) {
            int gc  = wn * 48 + ni * 8;
            int seg = gc >> 6;                       // 0=k, 1=q, 2=v
            int hb  = (gc & 63) + (lane & 3) * 2;
#pragma unroll
            for (int rr = 0; rr < 2; ++rr) {
                int gr = t0 + wm * 32 + mi * 16 + (lane >> 2) + rr * 8;
                float c0 = c[mi][ni][rr * 2], c1 = c[mi][ni][rr * 2 + 1];
                size_t off = (size_t)gr * HSn + hb;
                if (seg == 0) {
                    float r0 = c0 + __ldg(bk + hb);
                    float r1 = c1 + __ldg(bk + hb + 1);
                    __nv_bfloat16 h0 = __float2bfloat16(r0);
                    __nv_bfloat16 h1 = __float2bfloat16(r1);
                    g_kh[off]     = h0;
                    g_kh[off + 1] = h1;
                    g_kl[off]     = __float2bfloat16(r0 - __bfloat162float(h0));
                    g_kl[off + 1] = __float2bfloat16(r1 - __bfloat162float(h1));
                } else if (seg == 1) {
                    float q0 = c0 + __ldg(bq + hb);
                    float q1 = c1 + __ldg(bq + hb + 1);
                    *(float2*)(g_q + off) = make_float2(q0, q1);
                    float q80 = 8.0f * q0, q81 = 8.0f * q1;
                    __nv_bfloat16 h0 = __float2bfloat16(q80);
                    __nv_bfloat16 h1 = __float2bfloat16(q81);
                    g_qh[off]     = h0;
                    g_qh[off + 1] = h1;
                    g_ql[off]     = __float2bfloat16(q80 - __bfloat162float(h0));
                    g_ql[off + 1] = __float2bfloat16(q81 - __bfloat162float(h1));
                } else {
                    *(float2*)(g_v + off) =
                        make_float2(c0 + __ldg(bv + hb), c1 + __ldg(bv + hb + 1));
                }
            }
        }
    }
}

// ---------------------------------------------------------------------------
// K2: S = 8 q k^T via warp-level HMMA (verified in R13, rel_err 2.8e-5).
// ---------------------------------------------------------------------------
#define GM 128
#define GN 128
#define GS_AH 0
#define GS_AL 16384
#define GS_BH 32768
#define GS_BL 49152
#define GS_TOTAL 65536

__global__ __launch_bounds__(256, 2)
void qk_gemm_kernel(float* __restrict__ S)
{
    extern __shared__ char gsm[];
    const uint32_t sm0 = smem_u32(gsm);
    const int tid  = threadIdx.x;
    const int wid  = tid >> 5;
    const int lane = tid & 31;
    const int t0   = blockIdx.x * GM;
    const int v0   = blockIdx.y * GN;
    const int b    = blockIdx.z;
    const int wm   = wid & 1;
    const int wn   = wid >> 1;

    const char* qh = (const char*)(g_qh + ((size_t)b * Tn + t0) * HSn);
    const char* ql = (const char*)(g_ql + ((size_t)b * Tn + t0) * HSn);
    const char* kh = (const char*)(g_kh + ((size_t)b * Tn + v0) * HSn);
    const char* kl = (const char*)(g_kl + ((size_t)b * Tn + v0) * HSn);
    for (int idx = tid; idx < GM * 8; idx += 256) {
        int row = idx >> 3, c16 = idx & 7;
        int src = row * 128 + c16 * 16;
        uint32_t off = SW128((uint32_t)src);
        *(uint4*)(gsm + GS_AH + off) = *(const uint4*)(qh + src);
        *(uint4*)(gsm + GS_AL + off) = *(const uint4*)(ql + src);
        *(uint4*)(gsm + GS_BH + off) = *(const uint4*)(kh + src);
        *(uint4*)(gsm + GS_BL + off) = *(const uint4*)(kl + src);
    }
    __syncthreads();

    float c[4][4][4];
#pragma unroll
    for (int mi = 0; mi < 4; ++mi)
#pragma unroll
        for (int ni = 0; ni < 4; ++ni)
#pragma unroll
            for (int e = 0; e < 4; ++e) c[mi][ni][e] = 0.f;

    const int ar = (lane & 7) + ((lane >> 3) & 1) * 8;
    const int ac = (lane >> 4) * 8;

#pragma unroll
    for (int pass = 0; pass < 3; ++pass) {
        const uint32_t abase = sm0 + ((pass == 2) ? GS_AL : GS_AH);
        const uint32_t bbase = sm0 + ((pass == 1) ? GS_BL : GS_BH);
#pragma unroll
        for (int ks = 0; ks < 4; ++ks) {
            uint32_t a[4][4];
#pragma unroll
            for (int mi = 0; mi < 4; ++mi) {
                uint32_t byte = (uint32_t)((wm * 64 + mi * 16 + ar) * 128
                                           + (ks * 16 + ac) * 2);
                ldmatrix_x4(a[mi][0], a[mi][1], a[mi][2], a[mi][3],
                            abase + SW128(byte));
            }
            uint32_t bf[4][2];
#pragma unroll
            for (int np = 0; np < 2; ++np) {
                uint32_t byte = (uint32_t)((wn * 32 + np * 16 + ar) * 128
                                           + (ks * 16 + ac) * 2);
                uint32_t r0, r1, r2, r3;
                ldmatrix_x4(r0, r1, r2, r3, bbase + SW128(byte));
                bf[2 * np][0] = r0; bf[2 * np + 1][0] = r1;
                bf[2 * np][1] = r2; bf[2 * np + 1][1] = r3;
            }
#pragma unroll
            for (int mi = 0; mi < 4; ++mi)
#pragma unroll
                for (int ni = 0; ni < 4; ++ni)
                    mma_16816(c[mi][ni], a[mi], bf[ni][0], bf[ni][1]);
        }
    }

    float* Sb = S + (size_t)b * Tn * Tn;
#pragma unroll
    for (int mi = 0; mi < 4; ++mi) {
#pragma unroll
        for (int ni = 0; ni < 4; ++ni) {
            int gr = t0 + wm * 64 + mi * 16 + (lane >> 2);
            int gc = v0 + wn * 32 + ni * 8 + (lane & 3) * 2;
            *(float2*)(Sb + (size_t)gr * Tn + gc)       = make_float2(c[mi][ni][0], c[mi][ni][1]);
            *(float2*)(Sb + (size_t)(gr + 8) * Tn + gc) = make_float2(c[mi][ni][2], c[mi][ni][3]);
        }
    }
}

// ---------------------------------------------------------------------------
// K3: fused attention (R14 — measured 575us, FROZEN).
// Phase A/softmax warp = ONE t-row x ALL 8 batches (rel multiplicity 1).
// PV: warp = batch. 3 CTAs/SM.
// ---------------------------------------------------------------------------
#define RELBUF 16384                   // [tt8][hg4][v32] float4
#define Q_OFF  (3 * RELBUF)            // 49152: [b8][hg16][tt8] float4 = 16KB
#define PD_OFF (Q_OFF + 16384)         // 65536: [row8][b8][v32] float = 8KB
#define SC_OFF (PD_OFF + 8192)         // 73728: [row8][b8] float = 256B
#define ATTN_SMEM_BYTES (SC_OFF + 256) // 73984

__global__ __launch_bounds__(256, 3)
void attn_kernel(const float* __restrict__ rel)
{
    extern __shared__ float smf[];
    const uint32_t smem0 = smem_u32(smf);
    const uint32_t qu    = smem0 + Q_OFF;
    const uint32_t pdu   = smem0 + PD_OFF;

    const int tid  = threadIdx.x;
    const int w    = tid >> 5;           // phase A: row w ; PV: batch w
    const int lane = tid & 31;
    const int t0   = blockIdx.x * TQ;
    const int vbase = blockIdx.y * VLEN;

    {
        float4* sq4 = (float4*)(smf + (Q_OFF >> 2));
        for (int idx = tid; idx < 1024; idx += 256) {
            int tt = idx & 7, hg = (idx >> 3) & 15, b = idx >> 7;
            sq4[(b * 16 + hg) * 8 + tt] =
                *(const float4*)(g_q + ((size_t)b * Tn + t0 + tt) * HSn + hg * 4);
        }
    }

    const float* rsrc0 = rel + ((size_t)(t0 + (tid >> 7)) * Tn + vbase + (tid & 31)) * HSn
                             + ((tid >> 5) & 3) * 4;
    const uint32_t rdst0 = smem0 +
        (uint32_t)(((((tid >> 7) * 4 + ((tid >> 5) & 3)) * 32) + (tid & 31)) << 4);

    float m[8], l[8];
#pragma unroll
    for (int b = 0; b < 8; ++b) { m[b] = -1e30f; l[b] = 0.f; }

    ull oa2[8];
#pragma unroll
    for (int r = 0; r < 8; ++r) oa2[r] = 0ull;

    const float* vb = g_v + (size_t)w * Tn * HSn;
    const float* srow = g_s + (size_t)(t0 + w) * Tn;

#pragma unroll
    for (int c = 0; c < 4; ++c)
        cp_async16(rdst0 + c * 4096, rsrc0 + (size_t)c * 262144);
    CP_COMMIT();
#pragma unroll
    for (int c = 0; c < 4; ++c)
        cp_async16(rdst0 + RELBUF + c * 4096, rsrc0 + (size_t)c * 262144 + 16);
    CP_COMMIT();

    ull s2h[8];
    for (int s = 0; s < NSTG; ++s) {
        CP_WAIT(1);
        __syncthreads();

        if (s + 2 < NSTG) {
            const int s2 = s + 2;
            const float* sp = rsrc0 + (size_t)(s2 >> 2) * 2048 + (s2 & 3) * 16;
            uint32_t dp = rdst0 + (uint32_t)((s2 % 3) * RELBUF);
#pragma unroll
            for (int c = 0; c < 4; ++c)
                cp_async16(dp + c * 4096, sp + (size_t)c * 262144);
        }
        CP_COMMIT();

        const int tile = s >> 2, hq = s & 3;
        const int v0g  = vbase + tile * VT;
        const uint32_t relb = smem0 + (uint32_t)((s % 3) * RELBUF);

        if (hq == 0) {
#pragma unroll
            for (int b = 0; b < 8; ++b)
                s2h[b] = pack2(__ldg(srow + (size_t)b * Tn * Tn + v0g + lane), 0.f);
        }

#pragma unroll
        for (int hg = 0; hg < 4; ++hg) {
            ull r2a, r2b;
            lds_v2(r2a, r2b, relb + (uint32_t)((((w * 4 + hg) * 32) + lane) << 4));
            const int hgg = hq * 4 + hg;
            const uint32_t qb = qu + (uint32_t)(((hgg * 8) + w) << 4);
#pragma unroll
            for (int b = 0; b < 8; ++b) {
                ull q2a, q2b;
                lds_v2(q2a, q2b, qb + (uint32_t)((b * 16 * 8) << 4));
                s2h[b] = fma2(q2a, r2a, s2h[b]);
                s2h[b] = fma2(q2b, r2b, s2h[b]);
            }
        }

        if (hq == QPT - 1) {
#pragma unroll
            for (int b = 0; b < 8; ++b) {
                float xa, xb;
                unpack2(xa, xb, s2h[b]);
                float sv = xa + xb;
                float mt = sv;
#pragma unroll
                for (int o = 16; o > 0; o >>= 1)
                    mt = fmaxf(mt, __shfl_xor_sync(0xffffffffu, mt, o));
                float mn = fmaxf(m[b], mt);
                float sc = __expf(m[b] - mn);
                float p  = __expf(sv - mn);
                m[b] = mn;
                l[b] = l[b] * sc + p;
                sts_f32(pdu + (uint32_t)((((w * 8 + b) * 32) + lane) * 4), p);
                if (lane == 0) smf[(SC_OFF >> 2) + w * 8 + b] = sc;
            }
            __syncthreads();

#pragma unroll
            for (int r = 0; r < 8; ++r) {
                float scr = smf[(SC_OFF >> 2) + r * 8 + w];
                oa2[r] = mul2(oa2[r], pack2(scr, scr));
            }
            ull vc0, vc1, vn0, vn1;
            vc0 = ldg64(vb + (size_t)(v0g)     * HSn + 2 * lane);
            vc1 = ldg64(vb + (size_t)(v0g + 1) * HSn + 2 * lane);
#pragma unroll
            for (int vq = 0; vq < VT; vq += 2) {
                if (vq < VT - 2) {
                    vn0 = ldg64(vb + (size_t)(v0g + vq + 2) * HSn + 2 * lane);
                    vn1 = ldg64(vb + (size_t)(v0g + vq + 3) * HSn + 2 * lane);
                }
#pragma unroll
                for (int r = 0; r < 8; ++r) {
                    float p0, p1;
                    unpack2(p0, p1, lds64(pdu + (uint32_t)((((r * 8 + w) * 32) + vq) * 4)));
                    oa2[r] = fma2(pack2(p0, p0), vc0, oa2[r]);
                    oa2[r] = fma2(pack2(p1, p1), vc1, oa2[r]);
                }
                vc0 = vn0; vc1 = vn1;
            }
        }
    }

    const int sidx = blockIdx.y;
#pragma unroll
    for (int r = 0; r < 8; ++r) {
        int row = w * Tn + t0 + r;
        float o0, o1;
        unpack2(o0, o1, oa2[r]);
        ((float2*)(g_po[sidx] + (size_t)row * HSn))[lane] = make_float2(o0, o1);
    }
#pragma unroll
    for (int b = 0; b < 8; ++b) {
        float lt = l[b];
#pragma unroll
        for (int o = 16; o > 0; o >>= 1)
            lt += __shfl_xor_sync(0xffffffffu, lt, o);
        if (lane == 0) {
            int row = b * Tn + t0 + w;
            g_pm[sidx][row] = m[b];
            g_pl[sidx][row] = lt;
        }
    }
}

// ---------------------------------------------------------------------------
// K4: merge SPLIT partials -> normalized output (float4-vectorized)
// ---------------------------------------------------------------------------
__global__ __launch_bounds__(256)
void merge_kernel(float* __restrict__ out)
{
    int idx = blockIdx.x * 256 + threadIdx.x;
    int row = idx >> 4;
    float M = g_pm[0][row];
#pragma unroll
    for (int s = 1; s < SPLIT; ++s) M = fmaxf(M, g_pm[s][row]);
    float denom = 0.f;
    float4 acc = make_float4(0.f, 0.f, 0.f, 0.f);
#pragma unroll
    for (int s = 0; s < SPLIT; ++s) {
        float a = __expf(g_pm[s][row] - M);
        denom += a * g_pl[s][row];
        float4 p = ((const float4*)g_po[s])[idx];
        acc.x += a * p.x; acc.y += a * p.y; acc.z += a * p.z; acc.w += a * p.w;
    }
    float inv = 1.0f / denom;
    ((float4*)out)[idx] = make_float4(acc.x * inv, acc.y * inv, acc.z * inv, acc.w * inv);
}

// ---------------------------------------------------------------------------
extern "C" void kernel_launch(void* const* d_in, const int* in_sizes, int n_in,
                              void* d_out, int out_size)
{
    const float* x   = (const float*)d_in[0];
    const float* Wk  = (const float*)d_in[1];
    const float* bk  = (const float*)d_in[2];
    const float* Wq  = (const float*)d_in[3];
    const float* bq  = (const float*)d_in[4];
    const float* Wv  = (const float*)d_in[5];
    const float* bv  = (const float*)d_in[6];
    const float* rel = (const float*)d_in[7];
    float* out = (float*)d_out;

    cudaFuncSetAttribute(attn_kernel,
                         cudaFuncAttributeMaxDynamicSharedMemorySize, ATTN_SMEM_BYTES);
    cudaFuncSetAttribute(qk_gemm_kernel,
                         cudaFuncAttributeMaxDynamicSharedMemorySize, GS_TOTAL);
    cudaFuncSetAttribute(proj_hmma_kernel,
                         cudaFuncAttributeMaxDynamicSharedMemorySize, PS_TOTAL);

    float* d_s;
    cudaGetSymbolAddress((void**)&d_s, g_s);

    xcvt_kernel<<<(Bn * Tn * Dn) / 1024, 256>>>(x, Wk, Wq, Wv);               // idx 0
    proj_hmma_kernel<<<(Bn * Tn) / 64, 256, PS_TOTAL>>>(bk, bq, bv);          // idx 1
    qk_gemm_kernel<<<dim3(Tn / GM, Tn / GN, Bn), 256, GS_TOTAL>>>(d_s);       // idx 2
    attn_kernel<<<dim3(Tn / TQ, SPLIT), 256, ATTN_SMEM_BYTES>>>(rel);         // idx 3 (captured)
    merge_kernel<<<(Bn * Tn * HSn) / 1024, 256>>>(out);                       // idx 4

    (void)in_sizes; (void)n_in; (void)out_size;
}